// round 12
// baseline (speedup 1.0000x reference)
#include <cuda_runtime.h>
#include <cuda_bf16.h>
#include <cstdint>

#define NB 256
#define NH 256
#define NT 512
#define NL 128
#define NCTA 96
#define NTHR 256

// smem: A tile 128 rows x 1024B (128KB) | B tile 512 k-rows x 128B (64KB)
#define OFF_A    0
#define OFF_B    131072
#define ZS_STRIDE 68
#define OFF_ZS   OFF_B                                    // overlays B after MMA
#define OFF_YS   (OFF_B + 128 * ZS_STRIDE * 4)            // after zs
#define SMEM_BYTES (131072 + 65536)                       // 192 KB

// ---- global state (3-deep rings) ----
// h buffers: per (buf, nu): [hi plane | lo plane], each plane [256 k][64 n] bf16
__device__ uint8_t g_H0[3][4][65536];
__device__ uint8_t g_H1[3][4][65536];
__device__ float   g_P[3][32][128 * 64];      // layer1 x-partials [buf][pid][r][n]
__device__ float   g_Y[3][8][NB];             // y partials [buf][mu][b]

// ---- sync flags, one 128B line each (zeroed by host memset every launch) ----
// R0(nu): role0 steps done (count, 8/step). R2(nu): role2 steps done.
// A0R1(nu): role1 h0-consumption acks (count, 8/step).
// RP(pid): last P step written by role1-pid. AP(pid): last P step consumed.
// START: startup barrier.
#define NFLAGS 78
__device__ int g_flags[NFLAGS * 32];
#define FLG(i)     (&g_flags[(i) * 32])
#define F_R0(nu)   FLG(nu)
#define F_R2(nu)   FLG(4 + (nu))
#define F_A0R1(nu) FLG(8 + (nu))
#define F_RP(pid)  FLG(12 + (pid))
#define F_AP(pid)  FLG(44 + (pid))
#define F_START    FLG(76)

// ---------------- helpers ----------------
__device__ __forceinline__ float tanh_f(float x) {
    float t;
    asm("tanh.approx.f32 %0, %1;" : "=f"(t) : "f"(x));
    return t;
}
__device__ __forceinline__ float sigm(float x) {
    float t;
    asm("tanh.approx.f32 %0, %1;" : "=f"(t) : "f"(0.5f * x));
    return 0.5f * t + 0.5f;
}
__device__ __forceinline__ uint32_t s2u(const void* p) {
    uint32_t a;
    asm("{.reg .u64 t; cvta.to.shared.u64 t, %1; cvt.u32.u64 %0, t;}" : "=r"(a) : "l"(p));
    return a;
}
__device__ __forceinline__ uint32_t cvt2(float x, float y) {   // x->lo, y->hi
    uint32_t r;
    asm("cvt.rn.bf16x2.f32 %0, %1, %2;" : "=r"(r) : "f"(y), "f"(x));
    return r;
}
__device__ __forceinline__ float bf_lo(uint32_t u) {
    __nv_bfloat16_raw r; r.x = (unsigned short)(u & 0xffff);
    return __bfloat162float(*(__nv_bfloat16*)&r);
}
__device__ __forceinline__ float bf_hi(uint32_t u) {
    __nv_bfloat16_raw r; r.x = (unsigned short)(u >> 16);
    return __bfloat162float(*(__nv_bfloat16*)&r);
}
__device__ __forceinline__ void split2(float x, float y, uint32_t& hi, uint32_t& lo) {
    hi = cvt2(x, y);
    lo = cvt2(x - bf_lo(hi), y - bf_hi(hi));
}
__device__ __forceinline__ void ldsm4(uint32_t* r, uint32_t addr) {
    asm volatile("ldmatrix.sync.aligned.m8n8.x4.shared.b16 {%0,%1,%2,%3}, [%4];"
                 : "=r"(r[0]), "=r"(r[1]), "=r"(r[2]), "=r"(r[3]) : "r"(addr));
}
__device__ __forceinline__ void ldsm4t(uint32_t* r, uint32_t addr) {
    asm volatile("ldmatrix.sync.aligned.m8n8.x4.trans.shared.b16 {%0,%1,%2,%3}, [%4];"
                 : "=r"(r[0]), "=r"(r[1]), "=r"(r[2]), "=r"(r[3]) : "r"(addr));
}
__device__ __forceinline__ void mma16816(float* c, const uint32_t* a, const uint32_t* b) {
    asm volatile(
        "mma.sync.aligned.m16n8k16.row.col.f32.bf16.bf16.f32 "
        "{%0,%1,%2,%3}, {%4,%5,%6,%7}, {%8,%9}, {%0,%1,%2,%3};"
        : "+f"(c[0]), "+f"(c[1]), "+f"(c[2]), "+f"(c[3])
        : "r"(a[0]), "r"(a[1]), "r"(a[2]), "r"(a[3]), "r"(b[0]), "r"(b[1]));
}
__device__ __forceinline__ void cpasync16(uint32_t dst, const void* src) {
    asm volatile("cp.async.cg.shared.global [%0], [%1], 16;"
                 :: "r"(dst), "l"(src) : "memory");
}
__device__ __forceinline__ void wait_ge(volatile int* p, int target) {
    if (target <= 0) return;
    while (*p < target) { }
}

__global__ void __launch_bounds__(NTHR, 1)
lstm_mma_kernel(const float* __restrict__ latent,
                const float* __restrict__ W_lh,  const float* __restrict__ b_lh,
                const float* __restrict__ W_hh0, const float* __restrict__ b_ih0,
                const float* __restrict__ b_hh0,
                const float* __restrict__ W_ih1, const float* __restrict__ W_hh1,
                const float* __restrict__ b_ih1, const float* __restrict__ b_hh1,
                const float* __restrict__ W_ho,  const float* __restrict__ b_ho,
                float* __restrict__ out)
{
    extern __shared__ char smem[];
    const uint32_t sbase = s2u(smem);
    const int tid  = threadIdx.x;
    const int warp = tid >> 5;
    const int lane = tid & 31;

    const int bi   = blockIdx.x;
    const int role = bi >> 5;          // 0=hh0, 1=ih1, 2=hh1
    const int pid  = bi & 31;
    const int mu   = pid >> 2;         // unit tile (32 units)
    const int nu   = pid & 3;          // batch tile (64 batches)
    const int nbase = nu * 64;

    // ---- one-time: stage A = [Whi | Wlo] (128 rows x 512 k bf16, swizzled) ----
    {
        const float* Wsrc = (role == 0) ? W_hh0 : (role == 1) ? W_ih1 : W_hh1;
        for (int i = 0; i < 16; i++) {
            int idx = tid + i * NTHR;          // 0..4095
            int r = idx >> 5, kg = idx & 31;   // A-row, 8-col group
            int grow = (r & 3) * 256 + mu * 32 + (r >> 2);
            const float4* gp = (const float4*)(Wsrc + grow * 256 + kg * 8);
            float4 f0 = gp[0], f1 = gp[1];
            uint32_t h0, h1, h2, h3, l0, l1, l2, l3;
            split2(f0.x, f0.y, h0, l0);
            split2(f0.z, f0.w, h1, l1);
            split2(f1.x, f1.y, h2, l2);
            split2(f1.z, f1.w, h3, l3);
            int swr = r & 7;
            *(uint4*)(smem + OFF_A + r * 1024 + ((kg ^ swr) << 4))        = make_uint4(h0, h1, h2, h3);
            *(uint4*)(smem + OFF_A + r * 1024 + (((32 + kg) ^ swr) << 4)) = make_uint4(l0, l1, l2, l3);
        }
    }

    // ---- epilogue-thread constants: thread -> (unit jl, 8-col group cg8) ----
    const int jl  = tid >> 3;          // 0..31
    const int cg8 = tid & 7;           // 0..7
    const int j   = mu * 32 + jl;
    float bias[4] = {0.f, 0.f, 0.f, 0.f};
    if (role == 0) {
#pragma unroll
        for (int g = 0; g < 4; g++) bias[g] = b_ih0[g * NH + j] + b_hh0[g * NH + j];
    } else if (role == 2) {
#pragma unroll
        for (int g = 0; g < 4; g++) bias[g] = b_ih1[g * NH + j] + b_hh1[g * NH + j];
    }
    const float who = W_ho[j];
    const float bho = b_ho[0];

    // ---- init: h_init = latent @ W_lh.T + b_lh (roles 0,2 write h0(0)/h1(0)) ----
    if (role != 1) {
        uint16_t* hiP = (uint16_t*)((role == 0) ? g_H0[0][nu] : g_H1[0][nu]);
        for (int i = 0; i < 8; i++) {
            int idx = tid + i * NTHR;                // 0..2047
            int jj = mu * 32 + (idx & 31);
            int nn = idx >> 5;                       // 0..63 local batch
            float acc = b_lh[jj];
            for (int k = 0; k < NL; k += 4) {
                float4 lv = *(const float4*)(latent + (nbase + nn) * NL + k);
                float4 wv = *(const float4*)(W_lh + jj * NL + k);
                acc += lv.x * wv.x + lv.y * wv.y + lv.z * wv.z + lv.w * wv.w;
            }
            uint32_t hb = cvt2(acc, 0.f) & 0xffff;
            float lo = acc - bf_lo(hb);
            uint32_t lb = cvt2(lo, 0.f) & 0xffff;
            hiP[jj * 64 + nn]         = (uint16_t)hb;
            hiP[16384 + jj * 64 + nn] = (uint16_t)lb;
        }
    }

    float cst[8];
#pragma unroll
    for (int i = 0; i < 8; i++) cst[i] = 0.f;

    // ---- ldmatrix addressing ----
    const int swk  = lane & 7;
    const uint32_t aBase = sbase + OFF_A + (uint32_t)(warp * 16 + (lane & 15)) * 1024;
    const int aSel = lane >> 4;
    const int r7   = lane & 7;
    const int kh   = (lane >> 3) & 1;
    const int nsel = lane >> 4;
    uint32_t bOff[4];
#pragma unroll
    for (int p = 0; p < 4; p++)
        bOff[p] = sbase + OFF_B + (uint32_t)((kh * 8 + r7) * 128)
                + ((uint32_t)((p * 2 + nsel) ^ r7) << 4);

    float* zs = (float*)(smem + OFF_ZS);
    float* ys = (float*)(smem + OFF_YS);

    const int row0 = warp * 16 + (lane >> 2);
    const int colb = 2 * (lane & 3);

    // ---- startup barrier ----
    __syncthreads();
    if (tid == 0) {
        __threadfence();
        atomicAdd(F_START, 1);
        while (*(volatile int*)F_START < NCTA) { }
        __threadfence();
    }
    __syncthreads();

// stage the B tile (cp.async) from the given h ring slot
#define STAGE_B(srcptr) do {                                                 \
        const uint4* src_ = (const uint4*)(srcptr);                          \
        _Pragma("unroll")                                                    \
        for (int i = 0; i < 16; i++) {                                       \
            int idx = tid + i * NTHR;                                        \
            int krow = idx >> 3, c = idx & 7;                                \
            cpasync16(sbase + OFF_B + krow * 128 + ((c ^ (krow & 7)) << 4),  \
                      src_ + idx);                                           \
        }                                                                    \
        asm volatile("cp.async.commit_group;" ::: "memory");                 \
    } while (0)

// register double-buffered MMA over 16 chunks into acc[8][4]
#define RUN_MMA(acc) do {                                                    \
        uint32_t ah[2][4], al[2][4], bh[2][4][4], bl[2][4][4];               \
        { const int c0h_ = 0, c0l_ = 32;                                     \
          ldsm4(ah[0], aBase + (((c0h_ + aSel) ^ swk) << 4));                \
          ldsm4(al[0], aBase + (((c0l_ + aSel) ^ swk) << 4));                \
          _Pragma("unroll")                                                  \
          for (int p = 0; p < 4; p++) {                                      \
              ldsm4t(bh[0][p], bOff[p]);                                     \
              ldsm4t(bl[0][p], bOff[p] + 32768);                             \
          } }                                                                \
        _Pragma("unroll 2")                                                  \
        for (int ca = 0; ca < 16; ca++) {                                    \
            const int cur = ca & 1, nxt = cur ^ 1;                           \
            if (ca < 15) {                                                   \
                const int c0h_ = 2 * (ca + 1), c0l_ = 32 + 2 * (ca + 1);     \
                const uint32_t bstep_ = (uint32_t)(ca + 1) * 2048;           \
                ldsm4(ah[nxt], aBase + (((c0h_ + aSel) ^ swk) << 4));        \
                ldsm4(al[nxt], aBase + (((c0l_ + aSel) ^ swk) << 4));        \
                _Pragma("unroll")                                            \
                for (int p = 0; p < 4; p++) {                                \
                    ldsm4t(bh[nxt][p], bOff[p] + bstep_);                    \
                    ldsm4t(bl[nxt][p], bOff[p] + bstep_ + 32768);            \
                }                                                            \
            }                                                                \
            _Pragma("unroll")                                                \
            for (int nt = 0; nt < 8; nt++) {                                 \
                const uint32_t* bhf = &bh[cur][nt >> 1][(nt & 1) * 2];       \
                const uint32_t* blf = &bl[cur][nt >> 1][(nt & 1) * 2];       \
                mma16816(acc[nt], ah[cur], bhf);                             \
                mma16816(acc[nt], ah[cur], blf);                             \
                mma16816(acc[nt], al[cur], bhf);                             \
            }                                                                \
        }                                                                    \
    } while (0)

// epilogue: acc -> zs -> gates -> packed h store to Hb; role2 also fills ys
#define EPILOGUE(Hb, IS_R2) do {                                             \
        __syncthreads();                                                     \
        _Pragma("unroll")                                                    \
        for (int nt = 0; nt < 8; nt++) {                                     \
            int c = nt * 8 + colb;                                           \
            *(float2*)(zs + row0 * ZS_STRIDE + c)       = make_float2(acc[nt][0], acc[nt][1]); \
            *(float2*)(zs + (row0 + 8) * ZS_STRIDE + c) = make_float2(acc[nt][2], acc[nt][3]); \
        }                                                                    \
        __syncthreads();                                                     \
        const int rb = jl * 4;                                               \
        float4 zi4a = *(const float4*)(zs + (rb + 0) * ZS_STRIDE + cg8 * 8); \
        float4 zi4b = *(const float4*)(zs + (rb + 0) * ZS_STRIDE + cg8 * 8 + 4); \
        float4 zf4a = *(const float4*)(zs + (rb + 1) * ZS_STRIDE + cg8 * 8); \
        float4 zf4b = *(const float4*)(zs + (rb + 1) * ZS_STRIDE + cg8 * 8 + 4); \
        float4 zg4a = *(const float4*)(zs + (rb + 2) * ZS_STRIDE + cg8 * 8); \
        float4 zg4b = *(const float4*)(zs + (rb + 2) * ZS_STRIDE + cg8 * 8 + 4); \
        float4 zo4a = *(const float4*)(zs + (rb + 3) * ZS_STRIDE + cg8 * 8); \
        float4 zo4b = *(const float4*)(zs + (rb + 3) * ZS_STRIDE + cg8 * 8 + 4); \
        float ziv[8] = {zi4a.x, zi4a.y, zi4a.z, zi4a.w, zi4b.x, zi4b.y, zi4b.z, zi4b.w}; \
        float zfv[8] = {zf4a.x, zf4a.y, zf4a.z, zf4a.w, zf4b.x, zf4b.y, zf4b.z, zf4b.w}; \
        float zgv[8] = {zg4a.x, zg4a.y, zg4a.z, zg4a.w, zg4b.x, zg4b.y, zg4b.z, zg4b.w}; \
        float zov[8] = {zo4a.x, zo4a.y, zo4a.z, zo4a.w, zo4b.x, zo4b.y, zo4b.z, zo4b.w}; \
        float hv[8];                                                         \
        _Pragma("unroll")                                                    \
        for (int c = 0; c < 8; c++) {                                        \
            float zi = ziv[c] + bias[0];                                     \
            float zf = zfv[c] + bias[1];                                     \
            float zg = zgv[c] + bias[2];                                     \
            float zo = zov[c] + bias[3];                                     \
            cst[c] = sigm(zf) * cst[c] + sigm(zi) * tanh_f(zg);              \
            hv[c] = sigm(zo) * tanh_f(cst[c]);                               \
        }                                                                    \
        uint32_t hiu[4], lou[4];                                             \
        _Pragma("unroll")                                                    \
        for (int q = 0; q < 4; q++)                                          \
            split2(hv[2 * q], hv[2 * q + 1], hiu[q], lou[q]);                \
        __stcg((uint4*)((Hb) + j * 128 + cg8 * 16),                          \
               make_uint4(hiu[0], hiu[1], hiu[2], hiu[3]));                  \
        __stcg((uint4*)((Hb) + 32768 + j * 128 + cg8 * 16),                  \
               make_uint4(lou[0], lou[1], lou[2], lou[3]));                  \
        if (IS_R2) {                                                         \
            _Pragma("unroll")                                                \
            for (int c = 0; c < 8; c++)                                      \
                ys[(cg8 * 8 + c) * 33 + jl] = hv[c] * who;                   \
        }                                                                    \
    } while (0)

    // =====================================================================
    if (role == 0) {
        for (int t = 1; t <= NT; t++) {
            if (tid == 0) { wait_ge(F_R0(nu), 8 * (t - 1)); __threadfence(); }
            __syncthreads();
            STAGE_B(g_H0[(t - 1) % 3][nu]);
            if (tid == 0) wait_ge(F_A0R1(nu), 8 * (t - 3));   // h0(t-3) slot free
            asm volatile("cp.async.wait_group 0;" ::: "memory");
            __syncthreads();

            float acc[8][4];
#pragma unroll
            for (int nt = 0; nt < 8; nt++)
#pragma unroll
                for (int q = 0; q < 4; q++) acc[nt][q] = 0.f;
            RUN_MMA(acc);

            EPILOGUE(g_H0[t % 3][nu], 0);

            __syncthreads();
            if (tid == 0) { __threadfence(); atomicAdd(F_R0(nu), 1); }
        }
    } else if (role == 1) {
        for (int s = 1; s <= NT; s++) {
            if (tid == 0) { wait_ge(F_R0(nu), 8 * s); __threadfence(); }
            __syncthreads();
            STAGE_B(g_H0[s % 3][nu]);
            if (tid == 0) wait_ge(F_AP(pid), s - 3);          // P(s-3) slot free
            asm volatile("cp.async.wait_group 0;" ::: "memory");
            __syncthreads();
            if (tid == 0) atomicAdd(F_A0R1(nu), 1);           // done reading h0(s)

            float acc[8][4];
#pragma unroll
            for (int nt = 0; nt < 8; nt++)
#pragma unroll
                for (int q = 0; q < 4; q++) acc[nt][q] = 0.f;
            RUN_MMA(acc);

            float* Pd = g_P[s % 3][pid];
#pragma unroll
            for (int nt = 0; nt < 8; nt++) {
                int c = nt * 8 + colb;
                __stcg((float2*)(Pd + row0 * 64 + c), make_float2(acc[nt][0], acc[nt][1]));
                __stcg((float2*)(Pd + (row0 + 8) * 64 + c), make_float2(acc[nt][2], acc[nt][3]));
            }
            __syncthreads();
            if (tid == 0) { __threadfence(); *(volatile int*)F_RP(pid) = s; }
        }
    } else {
        for (int r = 1; r <= NT; r++) {
            if (tid == 0) {
                wait_ge(F_R2(nu), 8 * (r - 1));
                wait_ge(F_RP(pid), r);
                __threadfence();
            }
            __syncthreads();
            STAGE_B(g_H1[(r - 1) % 3][nu]);

            // prefetch P(r) while B lands
            float2 pv[16];
            {
                const float* Ps = g_P[r % 3][pid];
#pragma unroll
                for (int nt = 0; nt < 8; nt++) {
                    int c = nt * 8 + colb;
                    pv[nt]     = __ldcg((const float2*)(Ps + row0 * 64 + c));
                    pv[8 + nt] = __ldcg((const float2*)(Ps + (row0 + 8) * 64 + c));
                }
            }
            // out column r-2 from Y(r-1), hidden in the staging window
            if (mu == 0 && r >= 2 && tid >= 64 && tid < 128) {
                int b = tid - 64;
                float sY = bho;
#pragma unroll
                for (int m = 0; m < 8; m++)
                    sY += __ldcg(&g_Y[(r - 1) % 3][m][nbase + b]);
                out[(nbase + b) * NT + (r - 2)] = sY;
            }
            asm volatile("cp.async.wait_group 0;" ::: "memory");
            __syncthreads();

            float acc[8][4];
#pragma unroll
            for (int nt = 0; nt < 8; nt++)
#pragma unroll
                for (int q = 0; q < 4; q++) acc[nt][q] = 0.f;
            RUN_MMA(acc);
#pragma unroll
            for (int nt = 0; nt < 8; nt++) {
                acc[nt][0] += pv[nt].x;     acc[nt][1] += pv[nt].y;
                acc[nt][2] += pv[8 + nt].x; acc[nt][3] += pv[8 + nt].y;
            }
            if (tid == 0) *(volatile int*)F_AP(pid) = r;      // P(r) consumed

            EPILOGUE(g_H1[r % 3][nu], 1);

            __syncthreads();
            if (tid < 64) {
                float sY = 0.f;
#pragma unroll
                for (int k = 0; k < 32; k++) sY += ys[tid * 33 + k];
                __stcg(&g_Y[r % 3][mu][nbase + tid], sY);
            }
            __syncthreads();
            if (tid == 0) { __threadfence(); atomicAdd(F_R2(nu), 1); }
        }
        // final column 511 from Y(512)
        if (mu == 0) {
            if (tid == 0) { wait_ge(F_R2(nu), 8 * NT); __threadfence(); }
            __syncthreads();
            if (tid >= 64 && tid < 128) {
                int b = tid - 64;
                float sY = bho;
#pragma unroll
                for (int m = 0; m < 8; m++)
                    sY += __ldcg(&g_Y[NT % 3][m][nbase + b]);
                out[(nbase + b) * NT + (NT - 1)] = sY;
            }
        }
    }
}

extern "C" void kernel_launch(void* const* d_in, const int* in_sizes, int n_in,
                              void* d_out, int out_size)
{
    (void)in_sizes; (void)n_in; (void)out_size;
    cudaFuncSetAttribute(lstm_mma_kernel,
                         cudaFuncAttributeMaxDynamicSharedMemorySize, SMEM_BYTES);
    void* flgp = nullptr;
    cudaGetSymbolAddress(&flgp, g_flags);
    cudaMemsetAsync(flgp, 0, NFLAGS * 32 * sizeof(int));

    lstm_mma_kernel<<<NCTA, NTHR, SMEM_BYTES>>>(
        (const float*)d_in[0],   // latent
        (const float*)d_in[1],   // W_lh
        (const float*)d_in[2],   // b_lh
        // d_in[3] = W_ih0 unused (layer-0 input is all-zero)
        (const float*)d_in[4],   // W_hh0
        (const float*)d_in[5],   // b_ih0
        (const float*)d_in[6],   // b_hh0
        (const float*)d_in[7],   // W_ih1
        (const float*)d_in[8],   // W_hh1
        (const float*)d_in[9],   // b_ih1
        (const float*)d_in[10],  // b_hh1
        (const float*)d_in[11],  // W_ho
        (const float*)d_in[12],  // b_ho
        (float*)d_out);
}

// round 14
// speedup vs baseline: 1.1409x; 1.1409x over previous
#include <cuda_runtime.h>
#include <cuda_bf16.h>
#include <cstdint>

#define NB 256
#define NH 256
#define NT 512
#define NL 128
#define NCTA 96
#define NTHR 256
#define NTICK (NT + 4)   // 516

// smem: A tile 128 rows x 1024B (128KB) | B tile 512 k-rows x 128B (64KB)
#define OFF_A    0
#define OFF_B    131072
#define ZS_STRIDE 68
#define OFF_ZS   OFF_B                                    // overlays B after MMA
#define OFF_YS   (OFF_B + 128 * ZS_STRIDE * 4)            // after zs
#define SMEM_BYTES (131072 + 65536)                       // 192 KB

// ---- global state ----
__device__ uint8_t g_H0[2][4][65536];        // [buf][nu]: hi plane | lo plane, [k][n] bf16
__device__ uint8_t g_H1[2][4][65536];
__device__ float   g_P[2][32][128 * 64];     // layer1 x-partials [buf][pid][r][n]
__device__ float   g_Y[2][8][NB];            // y partials [buf][mu][b]
__device__ unsigned g_arrive;                // zeroed by cudaMemsetAsync each launch

// ---------------- helpers ----------------
__device__ __forceinline__ float tanh_f(float x) {
    float t;
    asm("tanh.approx.f32 %0, %1;" : "=f"(t) : "f"(x));
    return t;
}
__device__ __forceinline__ float sigm(float x) {
    float t;
    asm("tanh.approx.f32 %0, %1;" : "=f"(t) : "f"(0.5f * x));
    return 0.5f * t + 0.5f;
}
__device__ __forceinline__ uint32_t s2u(const void* p) {
    uint32_t a;
    asm("{.reg .u64 t; cvta.to.shared.u64 t, %1; cvt.u32.u64 %0, t;}" : "=r"(a) : "l"(p));
    return a;
}
__device__ __forceinline__ uint32_t cvt2(float x, float y) {   // x->lo, y->hi
    uint32_t r;
    asm("cvt.rn.bf16x2.f32 %0, %1, %2;" : "=r"(r) : "f"(y), "f"(x));
    return r;
}
__device__ __forceinline__ float bf_lo(uint32_t u) {
    __nv_bfloat16_raw r; r.x = (unsigned short)(u & 0xffff);
    return __bfloat162float(*(__nv_bfloat16*)&r);
}
__device__ __forceinline__ float bf_hi(uint32_t u) {
    __nv_bfloat16_raw r; r.x = (unsigned short)(u >> 16);
    return __bfloat162float(*(__nv_bfloat16*)&r);
}
__device__ __forceinline__ void split2(float x, float y, uint32_t& hi, uint32_t& lo) {
    hi = cvt2(x, y);
    lo = cvt2(x - bf_lo(hi), y - bf_hi(hi));
}
__device__ __forceinline__ void ldsm4(uint32_t* r, uint32_t addr) {
    asm volatile("ldmatrix.sync.aligned.m8n8.x4.shared.b16 {%0,%1,%2,%3}, [%4];"
                 : "=r"(r[0]), "=r"(r[1]), "=r"(r[2]), "=r"(r[3]) : "r"(addr));
}
__device__ __forceinline__ void ldsm4t(uint32_t* r, uint32_t addr) {
    asm volatile("ldmatrix.sync.aligned.m8n8.x4.trans.shared.b16 {%0,%1,%2,%3}, [%4];"
                 : "=r"(r[0]), "=r"(r[1]), "=r"(r[2]), "=r"(r[3]) : "r"(addr));
}
__device__ __forceinline__ void mma16816(float* c, const uint32_t* a, const uint32_t* b) {
    asm volatile(
        "mma.sync.aligned.m16n8k16.row.col.f32.bf16.bf16.f32 "
        "{%0,%1,%2,%3}, {%4,%5,%6,%7}, {%8,%9}, {%0,%1,%2,%3};"
        : "+f"(c[0]), "+f"(c[1]), "+f"(c[2]), "+f"(c[3])
        : "r"(a[0]), "r"(a[1]), "r"(a[2]), "r"(a[3]), "r"(b[0]), "r"(b[1]));
}
__device__ __forceinline__ void cpasync16(uint32_t dst, const void* src) {
    asm volatile("cp.async.cg.shared.global [%0], [%1], 16;"
                 :: "r"(dst), "l"(src) : "memory");
}
__device__ __forceinline__ void red_release(unsigned* p) {
    asm volatile("red.release.gpu.global.add.u32 [%0], 1;" :: "l"(p) : "memory");
}
__device__ __forceinline__ unsigned ld_acq(const unsigned* p) {
    unsigned v;
    asm volatile("ld.acquire.gpu.global.u32 %0, [%1];" : "=r"(v) : "l"(p) : "memory");
    return v;
}

__global__ void __launch_bounds__(NTHR, 1)
lstm_mma_kernel(const float* __restrict__ latent,
                const float* __restrict__ W_lh,  const float* __restrict__ b_lh,
                const float* __restrict__ W_hh0, const float* __restrict__ b_ih0,
                const float* __restrict__ b_hh0,
                const float* __restrict__ W_ih1, const float* __restrict__ W_hh1,
                const float* __restrict__ b_ih1, const float* __restrict__ b_hh1,
                const float* __restrict__ W_ho,  const float* __restrict__ b_ho,
                float* __restrict__ out)
{
    extern __shared__ char smem[];
    const uint32_t sbase = s2u(smem);
    const int tid  = threadIdx.x;
    const int warp = tid >> 5;
    const int lane = tid & 31;

    const int bi   = blockIdx.x;
    const int role = bi >> 5;          // 0=hh0, 1=ih1, 2=hh1
    const int pid  = bi & 31;
    const int mu   = pid >> 2;         // unit tile (32 units)
    const int nu   = pid & 3;          // batch tile (64 batches)
    const int nbase = nu * 64;

    // ---- one-time: stage A = [Whi | Wlo] (128 rows x 512 k bf16, swizzled) ----
    {
        const float* Wsrc = (role == 0) ? W_hh0 : (role == 1) ? W_ih1 : W_hh1;
        for (int i = 0; i < 16; i++) {
            int idx = tid + i * NTHR;          // 0..4095
            int r = idx >> 5, kg = idx & 31;   // A-row, 8-col group
            int grow = (r & 3) * 256 + mu * 32 + (r >> 2);
            const float4* gp = (const float4*)(Wsrc + grow * 256 + kg * 8);
            float4 f0 = gp[0], f1 = gp[1];
            uint32_t h0, h1, h2, h3, l0, l1, l2, l3;
            split2(f0.x, f0.y, h0, l0);
            split2(f0.z, f0.w, h1, l1);
            split2(f1.x, f1.y, h2, l2);
            split2(f1.z, f1.w, h3, l3);
            int swr = r & 7;
            *(uint4*)(smem + OFF_A + r * 1024 + ((kg ^ swr) << 4))        = make_uint4(h0, h1, h2, h3);
            *(uint4*)(smem + OFF_A + r * 1024 + (((32 + kg) ^ swr) << 4)) = make_uint4(l0, l1, l2, l3);
        }
    }

    // ---- epilogue-thread constants: thread -> (unit jl, 8-col group cg8) ----
    const int jl  = tid >> 3;          // 0..31
    const int cg8 = tid & 7;           // 0..7
    const int j   = mu * 32 + jl;
    float bias[4] = {0.f, 0.f, 0.f, 0.f};
    if (role == 0) {
#pragma unroll
        for (int g = 0; g < 4; g++) bias[g] = b_ih0[g * NH + j] + b_hh0[g * NH + j];
    } else if (role == 2) {
#pragma unroll
        for (int g = 0; g < 4; g++) bias[g] = b_ih1[g * NH + j] + b_hh1[g * NH + j];
    }
    const float who = W_ho[j];
    const float bho = b_ho[0];

    // ---- init: h_init = latent @ W_lh.T + b_lh (roles 0,2 write h0(0)/h1(0)) ----
    if (role != 1) {
        uint16_t* hiP = (uint16_t*)((role == 0) ? g_H0[0][nu] : g_H1[0][nu]);
        for (int i = 0; i < 8; i++) {
            int idx = tid + i * NTHR;                // 0..2047
            int jj = mu * 32 + (idx & 31);
            int nn = idx >> 5;                       // 0..63 local batch
            float acc0 = b_lh[jj];
            for (int k = 0; k < NL; k += 4) {
                float4 lv = *(const float4*)(latent + (nbase + nn) * NL + k);
                float4 wv = *(const float4*)(W_lh + jj * NL + k);
                acc0 += lv.x * wv.x + lv.y * wv.y + lv.z * wv.z + lv.w * wv.w;
            }
            uint32_t hb = cvt2(acc0, 0.f) & 0xffff;
            float lo = acc0 - bf_lo(hb);
            uint32_t lb = cvt2(lo, 0.f) & 0xffff;
            hiP[jj * 64 + nn]         = (uint16_t)hb;
            hiP[16384 + jj * 64 + nn] = (uint16_t)lb;
        }
    }

    float cst[8];
#pragma unroll
    for (int i = 0; i < 8; i++) cst[i] = 0.f;

    // ---- ldmatrix addressing (32x32 warp tiles: 4 row-tiles x 2 col-halves) ----
    const int wm = warp >> 1;          // row tile: rows 32*wm .. +31
    const int wn = warp & 1;           // col half: cols 32*wn .. +31
    const int swk  = lane & 7;
    const uint32_t aBase0 = sbase + OFF_A + (uint32_t)(wm * 32 + (lane & 15)) * 1024;
    const uint32_t aBase1 = aBase0 + 16 * 1024;
    const int aSel = lane >> 4;
    const int r7   = lane & 7;
    const int kh   = (lane >> 3) & 1;
    const int nsel = lane >> 4;
    uint32_t bOffW[2];
#pragma unroll
    for (int q = 0; q < 2; q++) {
        int p = 2 * wn + q;
        bOffW[q] = sbase + OFF_B + (uint32_t)((kh * 8 + r7) * 128)
                 + ((uint32_t)((p * 2 + nsel) ^ r7) << 4);
    }

    float* zs = (float*)(smem + OFF_ZS);
    float* ys = (float*)(smem + OFF_YS);

    const int rowA = 32 * wm + (lane >> 2);    // + 16*mt, +8 for frag halves
    const int colb = 2 * (lane & 3);
    const int cbase = 32 * wn + colb;

    // ---- startup barrier ----
    __syncthreads();
    if (tid == 0) {
        __threadfence();
        atomicAdd(&g_arrive, 1u);
        while (*(volatile unsigned*)&g_arrive < NCTA) { }
        __threadfence();
    }
    __syncthreads();
    unsigned bar = NCTA;

#define STAGE_B(srcptr) do {                                                 \
        const uint4* src_ = (const uint4*)(srcptr);                          \
        _Pragma("unroll")                                                    \
        for (int i = 0; i < 16; i++) {                                       \
            int idx = tid + i * NTHR;                                        \
            int krow = idx >> 3, c = idx & 7;                                \
            cpasync16(sbase + OFF_B + krow * 128 + ((c ^ (krow & 7)) << 4),  \
                      src_ + idx);                                           \
        }                                                                    \
        asm volatile("cp.async.commit_group;" ::: "memory");                 \
    } while (0)

#define LOADCHUNK(sl, ca_) do {                                              \
        const int c0h_ = 2 * (ca_), c0l_ = 32 + 2 * (ca_);                   \
        const uint32_t bstep_ = (uint32_t)(ca_) * 2048;                      \
        ldsm4(ah0[sl], aBase0 + (((c0h_ + aSel) ^ swk) << 4));               \
        ldsm4(ah1[sl], aBase1 + (((c0h_ + aSel) ^ swk) << 4));               \
        ldsm4(al0[sl], aBase0 + (((c0l_ + aSel) ^ swk) << 4));               \
        ldsm4(al1[sl], aBase1 + (((c0l_ + aSel) ^ swk) << 4));               \
        _Pragma("unroll")                                                    \
        for (int q = 0; q < 2; q++) {                                        \
            ldsm4t(bh[sl][q], bOffW[q] + bstep_);                            \
            ldsm4t(bl[sl][q], bOffW[q] + bstep_ + 32768);                    \
        }                                                                    \
    } while (0)

#define RUN_MMA(acc) do {                                                    \
        uint32_t ah0[2][4], ah1[2][4], al0[2][4], al1[2][4];                 \
        uint32_t bh[2][2][4], bl[2][2][4];                                   \
        LOADCHUNK(0, 0);                                                     \
        _Pragma("unroll 2")                                                  \
        for (int ca = 0; ca < 16; ca++) {                                    \
            const int cur = ca & 1, nxt = cur ^ 1;                           \
            if (ca < 15) LOADCHUNK(nxt, ca + 1);                             \
            _Pragma("unroll")                                                \
            for (int mt = 0; mt < 2; mt++) {                                 \
                const uint32_t* Ah = mt ? ah1[cur] : ah0[cur];               \
                const uint32_t* Al = mt ? al1[cur] : al0[cur];               \
                _Pragma("unroll")                                            \
                for (int nf = 0; nf < 4; nf++) {                             \
                    const uint32_t* bhf = &bh[cur][nf >> 1][(nf & 1) * 2];   \
                    const uint32_t* blf = &bl[cur][nf >> 1][(nf & 1) * 2];   \
                    mma16816(acc[mt][nf], Ah, bhf);                          \
                    mma16816(acc[mt][nf], Ah, blf);                          \
                    mma16816(acc[mt][nf], Al, bhf);                          \
                }                                                            \
            }                                                                \
        }                                                                    \
    } while (0)

    for (int tick = 1; tick <= NTICK; tick++) {
        const bool active = (role == 0) ? (tick <= NT)
                          : (role == 1) ? (tick >= 2 && tick <= NT + 1)
                                        : (tick >= 3 && tick <= NT + 2);
        // role1 computes y(h1(tick-3)) for ticks where tick-3 in [1, NT]
        const bool yact = (role == 1) && (tick >= 4 && tick <= NT + 3);

        // role1: prefetch h1(tick-3) row for the y-reduction (stable buffer:
        // role2 writes buf tick&1 this tick; we read buf (tick-1)&1)
        uint4 yh4 = make_uint4(0, 0, 0, 0), yl4 = make_uint4(0, 0, 0, 0);
        if (yact) {
            const uint8_t* H1s = g_H1[(tick - 1) & 1][nu];
            yh4 = __ldcg((const uint4*)(H1s + j * 128 + cg8 * 16));
            yl4 = __ldcg((const uint4*)(H1s + 32768 + j * 128 + cg8 * 16));
        }

        if (active) {
            STAGE_B((role == 2) ? g_H1[(tick - 1) & 1][nu] : g_H0[(tick - 1) & 1][nu]);

            // role2: prefetch this tick's P partials while B lands
            float2 pv0[2][4], pv1[2][4];
            if (role == 2) {
                const float* Ps = g_P[tick & 1][pid];
#pragma unroll
                for (int mt = 0; mt < 2; mt++)
#pragma unroll
                    for (int nf = 0; nf < 4; nf++) {
                        int r0 = rowA + 16 * mt;
                        int c = cbase + 8 * nf;
                        pv0[mt][nf] = __ldcg((const float2*)(Ps + r0 * 64 + c));
                        pv1[mt][nf] = __ldcg((const float2*)(Ps + (r0 + 8) * 64 + c));
                    }
            }

            asm volatile("cp.async.wait_group 0;" ::: "memory");
            __syncthreads();

            float acc[2][4][4];
#pragma unroll
            for (int mt = 0; mt < 2; mt++)
#pragma unroll
                for (int nf = 0; nf < 4; nf++)
#pragma unroll
                    for (int qq = 0; qq < 4; qq++) acc[mt][nf][qq] = 0.f;
            RUN_MMA(acc);

            if (role == 1) {
                float* Pd = g_P[(tick - 1) & 1][pid];
#pragma unroll
                for (int mt = 0; mt < 2; mt++)
#pragma unroll
                    for (int nf = 0; nf < 4; nf++) {
                        int r0 = rowA + 16 * mt;
                        int c = cbase + 8 * nf;
                        __stcg((float2*)(Pd + r0 * 64 + c),
                               make_float2(acc[mt][nf][0], acc[mt][nf][1]));
                        __stcg((float2*)(Pd + (r0 + 8) * 64 + c),
                               make_float2(acc[mt][nf][2], acc[mt][nf][3]));
                    }
            } else {
                if (role == 2) {
#pragma unroll
                    for (int mt = 0; mt < 2; mt++)
#pragma unroll
                        for (int nf = 0; nf < 4; nf++) {
                            acc[mt][nf][0] += pv0[mt][nf].x;
                            acc[mt][nf][1] += pv0[mt][nf].y;
                            acc[mt][nf][2] += pv1[mt][nf].x;
                            acc[mt][nf][3] += pv1[mt][nf].y;
                        }
                }
                __syncthreads();   // B reads done before zs overlays B
#pragma unroll
                for (int mt = 0; mt < 2; mt++)
#pragma unroll
                    for (int nf = 0; nf < 4; nf++) {
                        int r0 = rowA + 16 * mt;
                        int c = cbase + 8 * nf;
                        *(float2*)(zs + r0 * ZS_STRIDE + c) =
                            make_float2(acc[mt][nf][0], acc[mt][nf][1]);
                        *(float2*)(zs + (r0 + 8) * ZS_STRIDE + c) =
                            make_float2(acc[mt][nf][2], acc[mt][nf][3]);
                    }
                __syncthreads();

                // ---- gate nonlinearity + state update ----
                uint8_t* Hb = (role == 0) ? g_H0[tick & 1][nu] : g_H1[tick & 1][nu];
                const int rb = jl * 4;
                float4 zi4a = *(const float4*)(zs + (rb + 0) * ZS_STRIDE + cg8 * 8);
                float4 zi4b = *(const float4*)(zs + (rb + 0) * ZS_STRIDE + cg8 * 8 + 4);
                float4 zf4a = *(const float4*)(zs + (rb + 1) * ZS_STRIDE + cg8 * 8);
                float4 zf4b = *(const float4*)(zs + (rb + 1) * ZS_STRIDE + cg8 * 8 + 4);
                float4 zg4a = *(const float4*)(zs + (rb + 2) * ZS_STRIDE + cg8 * 8);
                float4 zg4b = *(const float4*)(zs + (rb + 2) * ZS_STRIDE + cg8 * 8 + 4);
                float4 zo4a = *(const float4*)(zs + (rb + 3) * ZS_STRIDE + cg8 * 8);
                float4 zo4b = *(const float4*)(zs + (rb + 3) * ZS_STRIDE + cg8 * 8 + 4);
                float ziv[8] = {zi4a.x, zi4a.y, zi4a.z, zi4a.w, zi4b.x, zi4b.y, zi4b.z, zi4b.w};
                float zfv[8] = {zf4a.x, zf4a.y, zf4a.z, zf4a.w, zf4b.x, zf4b.y, zf4b.z, zf4b.w};
                float zgv[8] = {zg4a.x, zg4a.y, zg4a.z, zg4a.w, zg4b.x, zg4b.y, zg4b.z, zg4b.w};
                float zov[8] = {zo4a.x, zo4a.y, zo4a.z, zo4a.w, zo4b.x, zo4b.y, zo4b.z, zo4b.w};
                float hv[8];
#pragma unroll
                for (int c = 0; c < 8; c++) {
                    float zi = ziv[c] + bias[0];
                    float zf = zfv[c] + bias[1];
                    float zg = zgv[c] + bias[2];
                    float zo = zov[c] + bias[3];
                    cst[c] = sigm(zf) * cst[c] + sigm(zi) * tanh_f(zg);
                    hv[c] = sigm(zo) * tanh_f(cst[c]);
                }
                uint32_t hiu[4], lou[4];
#pragma unroll
                for (int q = 0; q < 4; q++)
                    split2(hv[2 * q], hv[2 * q + 1], hiu[q], lou[q]);
                __stcg((uint4*)(Hb + j * 128 + cg8 * 16),
                       make_uint4(hiu[0], hiu[1], hiu[2], hiu[3]));
                __stcg((uint4*)(Hb + 32768 + j * 128 + cg8 * 16),
                       make_uint4(lou[0], lou[1], lou[2], lou[3]));
            }
        }

        // ---- role1: y reduction for h1(tick-3) (needs all 256 threads) ----
        if (yact) {
            __syncthreads();   // B LDSM reads done before ys overlays B region
            float yv[8];
            yv[0] = (bf_lo(yh4.x) + bf_lo(yl4.x)) * who;
            yv[1] = (bf_hi(yh4.x) + bf_hi(yl4.x)) * who;
            yv[2] = (bf_lo(yh4.y) + bf_lo(yl4.y)) * who;
            yv[3] = (bf_hi(yh4.y) + bf_hi(yl4.y)) * who;
            yv[4] = (bf_lo(yh4.z) + bf_lo(yl4.z)) * who;
            yv[5] = (bf_hi(yh4.z) + bf_hi(yl4.z)) * who;
            yv[6] = (bf_lo(yh4.w) + bf_lo(yl4.w)) * who;
            yv[7] = (bf_hi(yh4.w) + bf_hi(yl4.w)) * who;
#pragma unroll
            for (int c = 0; c < 8; c++)
                ys[(cg8 * 8 + c) * 33 + jl] = yv[c];
            __syncthreads();
            if (tid < 64) {
                float s = 0.f;
#pragma unroll
                for (int k = 0; k < 32; k++) s += ys[tid * 33 + k];
                __stcg(&g_Y[tick & 1][mu][nbase + tid], s);
            }
        }

        // ---- barrier: arrive (release), out-summer in the shadow, wait ----
        // Y[(tick-1)&1] holds y(h1(tick-4)) -> output column tick-5.
        __syncthreads();
        if (tid == 0) red_release(&g_arrive);

        if (role == 1 && mu == 0 && tick >= 5 && tid >= 64 && tid < 128) {
            int b = tid - 64;
            float s = bho;
#pragma unroll
            for (int m = 0; m < 8; m++)
                s += __ldcg(&g_Y[(tick - 1) & 1][m][nbase + b]);
            out[(nbase + b) * NT + (tick - 5)] = s;
        }

        bar += NCTA;
        if (tid == 0) {
            while (ld_acq(&g_arrive) < bar) { }
        }
        __syncthreads();
    }
}

extern "C" void kernel_launch(void* const* d_in, const int* in_sizes, int n_in,
                              void* d_out, int out_size)
{
    (void)in_sizes; (void)n_in; (void)out_size;
    cudaFuncSetAttribute(lstm_mma_kernel,
                         cudaFuncAttributeMaxDynamicSharedMemorySize, SMEM_BYTES);
    void* barp = nullptr;
    cudaGetSymbolAddress(&barp, g_arrive);
    cudaMemsetAsync(barp, 0, sizeof(unsigned));

    lstm_mma_kernel<<<NCTA, NTHR, SMEM_BYTES>>>(
        (const float*)d_in[0],   // latent
        (const float*)d_in[1],   // W_lh
        (const float*)d_in[2],   // b_lh
        // d_in[3] = W_ih0 unused (layer-0 input is all-zero)
        (const float*)d_in[4],   // W_hh0
        (const float*)d_in[5],   // b_ih0
        (const float*)d_in[6],   // b_hh0
        (const float*)d_in[7],   // W_ih1
        (const float*)d_in[8],   // W_hh1
        (const float*)d_in[9],   // b_ih1
        (const float*)d_in[10],  // b_hh1
        (const float*)d_in[11],  // W_ho
        (const float*)d_in[12],  // b_ho
        (float*)d_out);
}

// round 15
// speedup vs baseline: 1.1422x; 1.0011x over previous
#include <cuda_runtime.h>
#include <cuda_bf16.h>
#include <cstdint>

#define NB 256
#define NH 256
#define NT 512
#define NL 128
#define NCTA 96
#define NTHR 256
#define NTICK (NT + 4)   // 516
#define GRP 24           // CTAs per nu-group barrier

// smem: A tile 128 rows x 1024B (128KB) | B tile 512 k-rows x 128B (64KB)
#define OFF_A    0
#define OFF_B    131072
#define ZS_STRIDE 68
#define OFF_ZS   OFF_B                                    // overlays B after MMA
#define OFF_YS   (OFF_B + 128 * ZS_STRIDE * 4)            // after zs
#define SMEM_BYTES (131072 + 65536)                       // 192 KB

// ---- global state ----
__device__ uint8_t g_H0[2][4][65536];        // [buf][nu]: hi plane | lo plane, [k][n] bf16
__device__ uint8_t g_H1[2][4][65536];
__device__ float   g_P[2][32][128 * 64];     // layer1 x-partials [buf][pid][r][n]
__device__ float   g_Y[2][8][NB];            // y partials [buf][mu][b]
// sync: [0..3]*32 = per-nu tick counters, [4]*32 = startup. zeroed each launch.
__device__ unsigned g_sync[5 * 32];

// ---------------- helpers ----------------
__device__ __forceinline__ float tanh_f(float x) {
    float t;
    asm("tanh.approx.f32 %0, %1;" : "=f"(t) : "f"(x));
    return t;
}
__device__ __forceinline__ float sigm(float x) {
    float t;
    asm("tanh.approx.f32 %0, %1;" : "=f"(t) : "f"(0.5f * x));
    return 0.5f * t + 0.5f;
}
__device__ __forceinline__ uint32_t s2u(const void* p) {
    uint32_t a;
    asm("{.reg .u64 t; cvta.to.shared.u64 t, %1; cvt.u32.u64 %0, t;}" : "=r"(a) : "l"(p));
    return a;
}
__device__ __forceinline__ uint32_t cvt2(float x, float y) {   // x->lo, y->hi
    uint32_t r;
    asm("cvt.rn.bf16x2.f32 %0, %1, %2;" : "=r"(r) : "f"(y), "f"(x));
    return r;
}
__device__ __forceinline__ float bf_lo(uint32_t u) {
    __nv_bfloat16_raw r; r.x = (unsigned short)(u & 0xffff);
    return __bfloat162float(*(__nv_bfloat16*)&r);
}
__device__ __forceinline__ float bf_hi(uint32_t u) {
    __nv_bfloat16_raw r; r.x = (unsigned short)(u >> 16);
    return __bfloat162float(*(__nv_bfloat16*)&r);
}
__device__ __forceinline__ void split2(float x, float y, uint32_t& hi, uint32_t& lo) {
    hi = cvt2(x, y);
    lo = cvt2(x - bf_lo(hi), y - bf_hi(hi));
}
__device__ __forceinline__ void ldsm4(uint32_t* r, uint32_t addr) {
    asm volatile("ldmatrix.sync.aligned.m8n8.x4.shared.b16 {%0,%1,%2,%3}, [%4];"
                 : "=r"(r[0]), "=r"(r[1]), "=r"(r[2]), "=r"(r[3]) : "r"(addr));
}
__device__ __forceinline__ void ldsm4t(uint32_t* r, uint32_t addr) {
    asm volatile("ldmatrix.sync.aligned.m8n8.x4.trans.shared.b16 {%0,%1,%2,%3}, [%4];"
                 : "=r"(r[0]), "=r"(r[1]), "=r"(r[2]), "=r"(r[3]) : "r"(addr));
}
__device__ __forceinline__ void mma16816(float* c, const uint32_t* a, const uint32_t* b) {
    asm volatile(
        "mma.sync.aligned.m16n8k16.row.col.f32.bf16.bf16.f32 "
        "{%0,%1,%2,%3}, {%4,%5,%6,%7}, {%8,%9}, {%0,%1,%2,%3};"
        : "+f"(c[0]), "+f"(c[1]), "+f"(c[2]), "+f"(c[3])
        : "r"(a[0]), "r"(a[1]), "r"(a[2]), "r"(a[3]), "r"(b[0]), "r"(b[1]));
}
__device__ __forceinline__ void cpasync16(uint32_t dst, const void* src) {
    asm volatile("cp.async.cg.shared.global [%0], [%1], 16;"
                 :: "r"(dst), "l"(src) : "memory");
}
__device__ __forceinline__ void red_release(unsigned* p) {
    asm volatile("red.release.gpu.global.add.u32 [%0], 1;" :: "l"(p) : "memory");
}
__device__ __forceinline__ unsigned ld_acq(const unsigned* p) {
    unsigned v;
    asm volatile("ld.acquire.gpu.global.u32 %0, [%1];" : "=r"(v) : "l"(p) : "memory");
    return v;
}

__global__ void __launch_bounds__(NTHR, 1)
lstm_mma_kernel(const float* __restrict__ latent,
                const float* __restrict__ W_lh,  const float* __restrict__ b_lh,
                const float* __restrict__ W_hh0, const float* __restrict__ b_ih0,
                const float* __restrict__ b_hh0,
                const float* __restrict__ W_ih1, const float* __restrict__ W_hh1,
                const float* __restrict__ b_ih1, const float* __restrict__ b_hh1,
                const float* __restrict__ W_ho,  const float* __restrict__ b_ho,
                float* __restrict__ out)
{
    extern __shared__ char smem[];
    const uint32_t sbase = s2u(smem);
    const int tid  = threadIdx.x;
    const int warp = tid >> 5;
    const int lane = tid & 31;

    const int bi   = blockIdx.x;
    const int role = bi >> 5;          // 0=hh0, 1=ih1, 2=hh1
    const int pid  = bi & 31;
    const int mu   = pid >> 2;         // unit tile (32 units)
    const int nu   = pid & 3;          // batch tile (64 batches)
    const int nbase = nu * 64;
    unsigned* mybar = &g_sync[nu * 32];

    // ---- one-time: stage A = [Whi | Wlo] (128 rows x 512 k bf16, swizzled) ----
    {
        const float* Wsrc = (role == 0) ? W_hh0 : (role == 1) ? W_ih1 : W_hh1;
        for (int i = 0; i < 16; i++) {
            int idx = tid + i * NTHR;          // 0..4095
            int r = idx >> 5, kg = idx & 31;   // A-row, 8-col group
            int grow = (r & 3) * 256 + mu * 32 + (r >> 2);
            const float4* gp = (const float4*)(Wsrc + grow * 256 + kg * 8);
            float4 f0 = gp[0], f1 = gp[1];
            uint32_t h0, h1, h2, h3, l0, l1, l2, l3;
            split2(f0.x, f0.y, h0, l0);
            split2(f0.z, f0.w, h1, l1);
            split2(f1.x, f1.y, h2, l2);
            split2(f1.z, f1.w, h3, l3);
            int swr = r & 7;
            *(uint4*)(smem + OFF_A + r * 1024 + ((kg ^ swr) << 4))        = make_uint4(h0, h1, h2, h3);
            *(uint4*)(smem + OFF_A + r * 1024 + (((32 + kg) ^ swr) << 4)) = make_uint4(l0, l1, l2, l3);
        }
    }

    // ---- epilogue-thread constants: thread -> (unit jl, 8-col group cg8) ----
    const int jl  = tid >> 3;          // 0..31
    const int cg8 = tid & 7;           // 0..7
    const int j   = mu * 32 + jl;
    float bias[4] = {0.f, 0.f, 0.f, 0.f};
    if (role == 0) {
#pragma unroll
        for (int g = 0; g < 4; g++) bias[g] = b_ih0[g * NH + j] + b_hh0[g * NH + j];
    } else if (role == 2) {
#pragma unroll
        for (int g = 0; g < 4; g++) bias[g] = b_ih1[g * NH + j] + b_hh1[g * NH + j];
    }
    const float who = W_ho[j];
    const float bho = b_ho[0];

    // ---- init: h_init = latent @ W_lh.T + b_lh (roles 0,2 write h0(0)/h1(0)) ----
    if (role != 1) {
        uint16_t* hiP = (uint16_t*)((role == 0) ? g_H0[0][nu] : g_H1[0][nu]);
        for (int i = 0; i < 8; i++) {
            int idx = tid + i * NTHR;                // 0..2047
            int jj = mu * 32 + (idx & 31);
            int nn = idx >> 5;                       // 0..63 local batch
            float acc0 = b_lh[jj];
            for (int k = 0; k < NL; k += 4) {
                float4 lv = *(const float4*)(latent + (nbase + nn) * NL + k);
                float4 wv = *(const float4*)(W_lh + jj * NL + k);
                acc0 += lv.x * wv.x + lv.y * wv.y + lv.z * wv.z + lv.w * wv.w;
            }
            uint32_t hb = cvt2(acc0, 0.f) & 0xffff;
            float lo = acc0 - bf_lo(hb);
            uint32_t lb = cvt2(lo, 0.f) & 0xffff;
            hiP[jj * 64 + nn]         = (uint16_t)hb;
            hiP[16384 + jj * 64 + nn] = (uint16_t)lb;
        }
    }

    float cst[8];
#pragma unroll
    for (int i = 0; i < 8; i++) cst[i] = 0.f;

    // ---- ldmatrix addressing (32x32 warp tiles: 4 row-tiles x 2 col-halves) ----
    const int wm = warp >> 1;          // row tile: rows 32*wm .. +31
    const int wn = warp & 1;           // col half: cols 32*wn .. +31
    const int swk  = lane & 7;
    const uint32_t aBase0 = sbase + OFF_A + (uint32_t)(wm * 32 + (lane & 15)) * 1024;
    const uint32_t aBase1 = aBase0 + 16 * 1024;
    const int aSel = lane >> 4;
    const int r7   = lane & 7;
    const int kh   = (lane >> 3) & 1;
    const int nsel = lane >> 4;
    uint32_t bOffW[2];
#pragma unroll
    for (int q = 0; q < 2; q++) {
        int p = 2 * wn + q;
        bOffW[q] = sbase + OFF_B + (uint32_t)((kh * 8 + r7) * 128)
                 + ((uint32_t)((p * 2 + nsel) ^ r7) << 4);
    }

    float* zs = (float*)(smem + OFF_ZS);
    float* ys = (float*)(smem + OFF_YS);

    const int rowA = 32 * wm + (lane >> 2);    // + 16*mt, +8 for frag halves
    const int colb = 2 * (lane & 3);
    const int cbase = 32 * wn + colb;

    // ---- startup barrier (global, once) ----
    __syncthreads();
    if (tid == 0) {
        __threadfence();
        atomicAdd(&g_sync[4 * 32], 1u);
        while (*(volatile unsigned*)&g_sync[4 * 32] < NCTA) { }
        __threadfence();
    }
    __syncthreads();
    unsigned bar = 0;

#define STAGE_B(srcptr) do {                                                 \
        const uint4* src_ = (const uint4*)(srcptr);                          \
        _Pragma("unroll")                                                    \
        for (int i = 0; i < 16; i++) {                                       \
            int idx = tid + i * NTHR;                                        \
            int krow = idx >> 3, c = idx & 7;                                \
            cpasync16(sbase + OFF_B + krow * 128 + ((c ^ (krow & 7)) << 4),  \
                      src_ + idx);                                           \
        }                                                                    \
        asm volatile("cp.async.commit_group;" ::: "memory");                 \
    } while (0)

#define LOADCHUNK(sl, ca_) do {                                              \
        const int c0h_ = 2 * (ca_), c0l_ = 32 + 2 * (ca_);                   \
        const uint32_t bstep_ = (uint32_t)(ca_) * 2048;                      \
        ldsm4(ah0[sl], aBase0 + (((c0h_ + aSel) ^ swk) << 4));               \
        ldsm4(ah1[sl], aBase1 + (((c0h_ + aSel) ^ swk) << 4));               \
        ldsm4(al0[sl], aBase0 + (((c0l_ + aSel) ^ swk) << 4));               \
        ldsm4(al1[sl], aBase1 + (((c0l_ + aSel) ^ swk) << 4));               \
        _Pragma("unroll")                                                    \
        for (int q = 0; q < 2; q++) {                                        \
            ldsm4t(bh[sl][q], bOffW[q] + bstep_);                            \
            ldsm4t(bl[sl][q], bOffW[q] + bstep_ + 32768);                    \
        }                                                                    \
    } while (0)

#define RUN_MMA(acc) do {                                                    \
        uint32_t ah0[2][4], ah1[2][4], al0[2][4], al1[2][4];                 \
        uint32_t bh[2][2][4], bl[2][2][4];                                   \
        LOADCHUNK(0, 0);                                                     \
        _Pragma("unroll 2")                                                  \
        for (int ca = 0; ca < 16; ca++) {                                    \
            const int cur = ca & 1, nxt = cur ^ 1;                           \
            if (ca < 15) LOADCHUNK(nxt, ca + 1);                             \
            _Pragma("unroll")                                                \
            for (int mt = 0; mt < 2; mt++) {                                 \
                const uint32_t* Ah = mt ? ah1[cur] : ah0[cur];               \
                const uint32_t* Al = mt ? al1[cur] : al0[cur];               \
                _Pragma("unroll")                                            \
                for (int nf = 0; nf < 4; nf++) {                             \
                    const uint32_t* bhf = &bh[cur][nf >> 1][(nf & 1) * 2];   \
                    const uint32_t* blf = &bl[cur][nf >> 1][(nf & 1) * 2];   \
                    mma16816(acc[mt][nf], Ah, bhf);                          \
                    mma16816(acc[mt][nf], Ah, blf);                          \
                    mma16816(acc[mt][nf], Al, bhf);                          \
                }                                                            \
            }                                                                \
        }                                                                    \
    } while (0)

    for (int tick = 1; tick <= NTICK; tick++) {
        const bool active = (role == 0) ? (tick <= NT)
                          : (role == 1) ? (tick >= 2 && tick <= NT + 1)
                                        : (tick >= 3 && tick <= NT + 2);
        // role1 computes y(h1(tick-3)) for ticks where tick-3 in [1, NT]
        const bool yact = (role == 1) && (tick >= 4 && tick <= NT + 3);

        // role1: prefetch h1(tick-3) row for the y-reduction (stable buffer)
        uint4 yh4 = make_uint4(0, 0, 0, 0), yl4 = make_uint4(0, 0, 0, 0);
        if (yact) {
            const uint8_t* H1s = g_H1[(tick - 1) & 1][nu];
            yh4 = __ldcg((const uint4*)(H1s + j * 128 + cg8 * 16));
            yl4 = __ldcg((const uint4*)(H1s + 32768 + j * 128 + cg8 * 16));
        }

        if (active) {
            STAGE_B((role == 2) ? g_H1[(tick - 1) & 1][nu] : g_H0[(tick - 1) & 1][nu]);

            // role2: prefetch this tick's P partials while B lands
            float2 pv0[2][4], pv1[2][4];
            if (role == 2) {
                const float* Ps = g_P[tick & 1][pid];
#pragma unroll
                for (int mt = 0; mt < 2; mt++)
#pragma unroll
                    for (int nf = 0; nf < 4; nf++) {
                        int r0 = rowA + 16 * mt;
                        int c = cbase + 8 * nf;
                        pv0[mt][nf] = __ldcg((const float2*)(Ps + r0 * 64 + c));
                        pv1[mt][nf] = __ldcg((const float2*)(Ps + (r0 + 8) * 64 + c));
                    }
            }

            asm volatile("cp.async.wait_group 0;" ::: "memory");
            __syncthreads();

            float acc[2][4][4];
#pragma unroll
            for (int mt = 0; mt < 2; mt++)
#pragma unroll
                for (int nf = 0; nf < 4; nf++)
#pragma unroll
                    for (int qq = 0; qq < 4; qq++) acc[mt][nf][qq] = 0.f;
            RUN_MMA(acc);

            if (role == 1) {
                float* Pd = g_P[(tick - 1) & 1][pid];
#pragma unroll
                for (int mt = 0; mt < 2; mt++)
#pragma unroll
                    for (int nf = 0; nf < 4; nf++) {
                        int r0 = rowA + 16 * mt;
                        int c = cbase + 8 * nf;
                        __stcg((float2*)(Pd + r0 * 64 + c),
                               make_float2(acc[mt][nf][0], acc[mt][nf][1]));
                        __stcg((float2*)(Pd + (r0 + 8) * 64 + c),
                               make_float2(acc[mt][nf][2], acc[mt][nf][3]));
                    }
            } else {
                if (role == 2) {
#pragma unroll
                    for (int mt = 0; mt < 2; mt++)
#pragma unroll
                        for (int nf = 0; nf < 4; nf++) {
                            acc[mt][nf][0] += pv0[mt][nf].x;
                            acc[mt][nf][1] += pv0[mt][nf].y;
                            acc[mt][nf][2] += pv1[mt][nf].x;
                            acc[mt][nf][3] += pv1[mt][nf].y;
                        }
                }
                __syncthreads();   // B reads done before zs overlays B
#pragma unroll
                for (int mt = 0; mt < 2; mt++)
#pragma unroll
                    for (int nf = 0; nf < 4; nf++) {
                        int r0 = rowA + 16 * mt;
                        int c = cbase + 8 * nf;
                        *(float2*)(zs + r0 * ZS_STRIDE + c) =
                            make_float2(acc[mt][nf][0], acc[mt][nf][1]);
                        *(float2*)(zs + (r0 + 8) * ZS_STRIDE + c) =
                            make_float2(acc[mt][nf][2], acc[mt][nf][3]);
                    }
                __syncthreads();

                // ---- gate nonlinearity + state update ----
                uint8_t* Hb = (role == 0) ? g_H0[tick & 1][nu] : g_H1[tick & 1][nu];
                const int rb = jl * 4;
                float4 zi4a = *(const float4*)(zs + (rb + 0) * ZS_STRIDE + cg8 * 8);
                float4 zi4b = *(const float4*)(zs + (rb + 0) * ZS_STRIDE + cg8 * 8 + 4);
                float4 zf4a = *(const float4*)(zs + (rb + 1) * ZS_STRIDE + cg8 * 8);
                float4 zf4b = *(const float4*)(zs + (rb + 1) * ZS_STRIDE + cg8 * 8 + 4);
                float4 zg4a = *(const float4*)(zs + (rb + 2) * ZS_STRIDE + cg8 * 8);
                float4 zg4b = *(const float4*)(zs + (rb + 2) * ZS_STRIDE + cg8 * 8 + 4);
                float4 zo4a = *(const float4*)(zs + (rb + 3) * ZS_STRIDE + cg8 * 8);
                float4 zo4b = *(const float4*)(zs + (rb + 3) * ZS_STRIDE + cg8 * 8 + 4);
                float ziv[8] = {zi4a.x, zi4a.y, zi4a.z, zi4a.w, zi4b.x, zi4b.y, zi4b.z, zi4b.w};
                float zfv[8] = {zf4a.x, zf4a.y, zf4a.z, zf4a.w, zf4b.x, zf4b.y, zf4b.z, zf4b.w};
                float zgv[8] = {zg4a.x, zg4a.y, zg4a.z, zg4a.w, zg4b.x, zg4b.y, zg4b.z, zg4b.w};
                float zov[8] = {zo4a.x, zo4a.y, zo4a.z, zo4a.w, zo4b.x, zo4b.y, zo4b.z, zo4b.w};
                float hv[8];
#pragma unroll
                for (int c = 0; c < 8; c++) {
                    float zi = ziv[c] + bias[0];
                    float zf = zfv[c] + bias[1];
                    float zg = zgv[c] + bias[2];
                    float zo = zov[c] + bias[3];
                    cst[c] = sigm(zf) * cst[c] + sigm(zi) * tanh_f(zg);
                    hv[c] = sigm(zo) * tanh_f(cst[c]);
                }
                uint32_t hiu[4], lou[4];
#pragma unroll
                for (int q = 0; q < 4; q++)
                    split2(hv[2 * q], hv[2 * q + 1], hiu[q], lou[q]);
                __stcg((uint4*)(Hb + j * 128 + cg8 * 16),
                       make_uint4(hiu[0], hiu[1], hiu[2], hiu[3]));
                __stcg((uint4*)(Hb + 32768 + j * 128 + cg8 * 16),
                       make_uint4(lou[0], lou[1], lou[2], lou[3]));
            }
        }

        // ---- role1: y reduction for h1(tick-3) (needs all 256 threads) ----
        if (yact) {
            __syncthreads();   // B LDSM reads done before ys overlays B region
            float yv[8];
            yv[0] = (bf_lo(yh4.x) + bf_lo(yl4.x)) * who;
            yv[1] = (bf_hi(yh4.x) + bf_hi(yl4.x)) * who;
            yv[2] = (bf_lo(yh4.y) + bf_lo(yl4.y)) * who;
            yv[3] = (bf_hi(yh4.y) + bf_hi(yl4.y)) * who;
            yv[4] = (bf_lo(yh4.z) + bf_lo(yl4.z)) * who;
            yv[5] = (bf_hi(yh4.z) + bf_hi(yl4.z)) * who;
            yv[6] = (bf_lo(yh4.w) + bf_lo(yl4.w)) * who;
            yv[7] = (bf_hi(yh4.w) + bf_hi(yl4.w)) * who;
#pragma unroll
            for (int c = 0; c < 8; c++)
                ys[(cg8 * 8 + c) * 33 + jl] = yv[c];
            __syncthreads();
            if (tid < 64) {
                float s = 0.f;
#pragma unroll
                for (int k = 0; k < 32; k++) s += ys[tid * 33 + k];
                __stcg(&g_Y[tick & 1][mu][nbase + tid], s);
            }
        }

        // ---- per-nu barrier: arrive (release), out-summer in shadow, wait ----
        // Y[(tick-1)&1] holds y(h1(tick-4)) -> output column tick-5.
        __syncthreads();
        if (tid == 0) red_release(mybar);

        if (role == 1 && mu == 0 && tick >= 5 && tid >= 64 && tid < 128) {
            int b = tid - 64;
            float s = bho;
#pragma unroll
            for (int m = 0; m < 8; m++)
                s += __ldcg(&g_Y[(tick - 1) & 1][m][nbase + b]);
            out[(nbase + b) * NT + (tick - 5)] = s;
        }

        bar += GRP;
        if (tid == 0) {
            while (ld_acq(mybar) < bar) { }
        }
        __syncthreads();
    }
}

extern "C" void kernel_launch(void* const* d_in, const int* in_sizes, int n_in,
                              void* d_out, int out_size)
{
    (void)in_sizes; (void)n_in; (void)out_size;
    cudaFuncSetAttribute(lstm_mma_kernel,
                         cudaFuncAttributeMaxDynamicSharedMemorySize, SMEM_BYTES);
    void* syncp = nullptr;
    cudaGetSymbolAddress(&syncp, g_sync);
    cudaMemsetAsync(syncp, 0, 5 * 32 * sizeof(unsigned));

    lstm_mma_kernel<<<NCTA, NTHR, SMEM_BYTES>>>(
        (const float*)d_in[0],   // latent
        (const float*)d_in[1],   // W_lh
        (const float*)d_in[2],   // b_lh
        // d_in[3] = W_ih0 unused (layer-0 input is all-zero)
        (const float*)d_in[4],   // W_hh0
        (const float*)d_in[5],   // b_ih0
        (const float*)d_in[6],   // b_hh0
        (const float*)d_in[7],   // W_ih1
        (const float*)d_in[8],   // W_hh1
        (const float*)d_in[9],   // b_ih1
        (const float*)d_in[10],  // b_hh1
        (const float*)d_in[11],  // W_ho
        (const float*)d_in[12],  // b_ho
        (float*)d_out);
}

// round 16
// speedup vs baseline: 1.1617x; 1.0171x over previous
#include <cuda_runtime.h>
#include <cuda_bf16.h>
#include <cstdint>

#define NB 256
#define NH 256
#define NT 512
#define NL 128
#define NCTA 96
#define NTHR 512
#define NTICK (NT + 4)   // 516
#define GRP 24           // CTAs per nu-group barrier

// smem: A tile 128 rows x 1024B (128KB) | B tile 512 k-rows x 128B (64KB)
#define OFF_A    0
#define OFF_B    131072
#define ZS_STRIDE 68
#define OFF_ZS   OFF_B                                    // overlays B after MMA
#define OFF_YS   (OFF_B + 128 * ZS_STRIDE * 4)            // after zs
#define SMEM_BYTES (131072 + 65536)                       // 192 KB

// ---- global state ----
__device__ uint8_t g_H0[2][4][65536];        // [buf][nu]: hi plane | lo plane, [k][n] bf16
__device__ uint8_t g_H1[2][4][65536];
__device__ float   g_P[2][32][128 * 64];     // layer1 x-partials [buf][pid][r][n]
__device__ float   g_Y[2][8][NB];            // y partials [buf][mu][b]
// sync: [0..3]*32 = per-nu tick counters, [4]*32 = startup. zeroed each launch.
__device__ unsigned g_sync[5 * 32];

// ---------------- helpers ----------------
__device__ __forceinline__ float tanh_f(float x) {
    float t;
    asm("tanh.approx.f32 %0, %1;" : "=f"(t) : "f"(x));
    return t;
}
__device__ __forceinline__ float sigm(float x) {
    float t;
    asm("tanh.approx.f32 %0, %1;" : "=f"(t) : "f"(0.5f * x));
    return 0.5f * t + 0.5f;
}
__device__ __forceinline__ uint32_t s2u(const void* p) {
    uint32_t a;
    asm("{.reg .u64 t; cvta.to.shared.u64 t, %1; cvt.u32.u64 %0, t;}" : "=r"(a) : "l"(p));
    return a;
}
__device__ __forceinline__ uint32_t cvt2(float x, float y) {   // x->lo, y->hi
    uint32_t r;
    asm("cvt.rn.bf16x2.f32 %0, %1, %2;" : "=r"(r) : "f"(y), "f"(x));
    return r;
}
__device__ __forceinline__ float bf_lo(uint32_t u) {
    __nv_bfloat16_raw r; r.x = (unsigned short)(u & 0xffff);
    return __bfloat162float(*(__nv_bfloat16*)&r);
}
__device__ __forceinline__ float bf_hi(uint32_t u) {
    __nv_bfloat16_raw r; r.x = (unsigned short)(u >> 16);
    return __bfloat162float(*(__nv_bfloat16*)&r);
}
__device__ __forceinline__ void split2(float x, float y, uint32_t& hi, uint32_t& lo) {
    hi = cvt2(x, y);
    lo = cvt2(x - bf_lo(hi), y - bf_hi(hi));
}
__device__ __forceinline__ void ldsm4(uint32_t* r, uint32_t addr) {
    asm volatile("ldmatrix.sync.aligned.m8n8.x4.shared.b16 {%0,%1,%2,%3}, [%4];"
                 : "=r"(r[0]), "=r"(r[1]), "=r"(r[2]), "=r"(r[3]) : "r"(addr));
}
__device__ __forceinline__ void ldsm4t(uint32_t* r, uint32_t addr) {
    asm volatile("ldmatrix.sync.aligned.m8n8.x4.trans.shared.b16 {%0,%1,%2,%3}, [%4];"
                 : "=r"(r[0]), "=r"(r[1]), "=r"(r[2]), "=r"(r[3]) : "r"(addr));
}
__device__ __forceinline__ void mma16816(float* c, const uint32_t* a, const uint32_t* b) {
    asm volatile(
        "mma.sync.aligned.m16n8k16.row.col.f32.bf16.bf16.f32 "
        "{%0,%1,%2,%3}, {%4,%5,%6,%7}, {%8,%9}, {%0,%1,%2,%3};"
        : "+f"(c[0]), "+f"(c[1]), "+f"(c[2]), "+f"(c[3])
        : "r"(a[0]), "r"(a[1]), "r"(a[2]), "r"(a[3]), "r"(b[0]), "r"(b[1]));
}
__device__ __forceinline__ void cpasync16(uint32_t dst, const void* src) {
    asm volatile("cp.async.cg.shared.global [%0], [%1], 16;"
                 :: "r"(dst), "l"(src) : "memory");
}
__device__ __forceinline__ void red_release(unsigned* p) {
    asm volatile("red.release.gpu.global.add.u32 [%0], 1;" :: "l"(p) : "memory");
}
__device__ __forceinline__ unsigned ld_acq(const unsigned* p) {
    unsigned v;
    asm volatile("ld.acquire.gpu.global.u32 %0, [%1];" : "=r"(v) : "l"(p) : "memory");
    return v;
}

__global__ void __launch_bounds__(NTHR, 1)
lstm_mma_kernel(const float* __restrict__ latent,
                const float* __restrict__ W_lh,  const float* __restrict__ b_lh,
                const float* __restrict__ W_hh0, const float* __restrict__ b_ih0,
                const float* __restrict__ b_hh0,
                const float* __restrict__ W_ih1, const float* __restrict__ W_hh1,
                const float* __restrict__ b_ih1, const float* __restrict__ b_hh1,
                const float* __restrict__ W_ho,  const float* __restrict__ b_ho,
                float* __restrict__ out)
{
    extern __shared__ char smem[];
    const uint32_t sbase = s2u(smem);
    const int tid  = threadIdx.x;
    const int warp = tid >> 5;
    const int lane = tid & 31;

    const int bi   = blockIdx.x;
    const int role = bi >> 5;          // 0=hh0, 1=ih1, 2=hh1
    const int pid  = bi & 31;
    const int mu   = pid >> 2;         // unit tile (32 units)
    const int nu   = pid & 3;          // batch tile (64 batches)
    const int nbase = nu * 64;
    unsigned* mybar = &g_sync[nu * 32];

    // ---- one-time: stage A = [Whi | Wlo] (128 rows x 512 k bf16, swizzled) ----
    {
        const float* Wsrc = (role == 0) ? W_hh0 : (role == 1) ? W_ih1 : W_hh1;
        for (int i = 0; i < 8; i++) {
            int idx = tid + i * NTHR;          // 0..4095
            int r = idx >> 5, kg = idx & 31;   // A-row, 8-col group
            int grow = (r & 3) * 256 + mu * 32 + (r >> 2);
            const float4* gp = (const float4*)(Wsrc + grow * 256 + kg * 8);
            float4 f0 = gp[0], f1 = gp[1];
            uint32_t h0, h1, h2, h3, l0, l1, l2, l3;
            split2(f0.x, f0.y, h0, l0);
            split2(f0.z, f0.w, h1, l1);
            split2(f1.x, f1.y, h2, l2);
            split2(f1.z, f1.w, h3, l3);
            int swr = r & 7;
            *(uint4*)(smem + OFF_A + r * 1024 + ((kg ^ swr) << 4))        = make_uint4(h0, h1, h2, h3);
            *(uint4*)(smem + OFF_A + r * 1024 + (((32 + kg) ^ swr) << 4)) = make_uint4(l0, l1, l2, l3);
        }
    }

    // ---- epilogue-thread constants: thread -> (unit jl, 4-col group cg4) ----
    const int jl  = tid >> 4;          // 0..31
    const int cg4 = tid & 15;          // 0..15 (cols cg4*4 .. +3)
    const int j   = mu * 32 + jl;
    float bias[4] = {0.f, 0.f, 0.f, 0.f};
    if (role == 0) {
#pragma unroll
        for (int g = 0; g < 4; g++) bias[g] = b_ih0[g * NH + j] + b_hh0[g * NH + j];
    } else if (role == 2) {
#pragma unroll
        for (int g = 0; g < 4; g++) bias[g] = b_ih1[g * NH + j] + b_hh1[g * NH + j];
    }
    const float who = W_ho[j];
    const float bho = b_ho[0];

    // ---- init: h_init = latent @ W_lh.T + b_lh (roles 0,2 write h0(0)/h1(0)) ----
    if (role != 1) {
        uint16_t* hiP = (uint16_t*)((role == 0) ? g_H0[0][nu] : g_H1[0][nu]);
        for (int i = 0; i < 4; i++) {
            int idx = tid + i * NTHR;                // 0..2047
            int jj = mu * 32 + (idx & 31);
            int nn = idx >> 5;                       // 0..63 local batch
            float acc0 = b_lh[jj];
            for (int k = 0; k < NL; k += 4) {
                float4 lv = *(const float4*)(latent + (nbase + nn) * NL + k);
                float4 wv = *(const float4*)(W_lh + jj * NL + k);
                acc0 += lv.x * wv.x + lv.y * wv.y + lv.z * wv.z + lv.w * wv.w;
            }
            uint32_t hb = cvt2(acc0, 0.f) & 0xffff;
            float lo = acc0 - bf_lo(hb);
            uint32_t lb = cvt2(lo, 0.f) & 0xffff;
            hiP[jj * 64 + nn]         = (uint16_t)hb;
            hiP[16384 + jj * 64 + nn] = (uint16_t)lb;
        }
    }

    float cst[4] = {0.f, 0.f, 0.f, 0.f};

    // ---- ldmatrix addressing (16x32 warp tiles: 8 row-tiles x 2 col-halves) ----
    const int wm = warp >> 1;          // row tile: rows 16*wm .. +15
    const int wn = warp & 1;           // col half: cols 32*wn .. +31
    const int swk  = lane & 7;
    const uint32_t aBase = sbase + OFF_A + (uint32_t)(wm * 16 + (lane & 15)) * 1024;
    const int aSel = lane >> 4;
    const int r7   = lane & 7;
    const int kh   = (lane >> 3) & 1;
    const int nsel = lane >> 4;
    uint32_t bOffW[2];
#pragma unroll
    for (int q = 0; q < 2; q++) {
        int p = 2 * wn + q;
        bOffW[q] = sbase + OFF_B + (uint32_t)((kh * 8 + r7) * 128)
                 + ((uint32_t)((p * 2 + nsel) ^ r7) << 4);
    }

    float* zs = (float*)(smem + OFF_ZS);
    float* ys = (float*)(smem + OFF_YS);

    const int rowA = 16 * wm + (lane >> 2);    // +8 for second frag row
    const int colb = 2 * (lane & 3);
    const int cbase = 32 * wn + colb;

    // ---- startup barrier (global, once) ----
    __syncthreads();
    if (tid == 0) {
        __threadfence();
        atomicAdd(&g_sync[4 * 32], 1u);
        while (*(volatile unsigned*)&g_sync[4 * 32] < NCTA) { }
        __threadfence();
    }
    __syncthreads();
    unsigned bar = 0;

#define STAGE_B(srcptr) do {                                                 \
        const uint4* src_ = (const uint4*)(srcptr);                          \
        _Pragma("unroll")                                                    \
        for (int i = 0; i < 8; i++) {                                        \
            int idx = tid + i * NTHR;                                        \
            int krow = idx >> 3, c = idx & 7;                                \
            cpasync16(sbase + OFF_B + krow * 128 + ((c ^ (krow & 7)) << 4),  \
                      src_ + idx);                                           \
        }                                                                    \
        asm volatile("cp.async.commit_group;" ::: "memory");                 \
    } while (0)

#define LOADCHUNK(sl, ca_) do {                                              \
        const int c0h_ = 2 * (ca_), c0l_ = 32 + 2 * (ca_);                   \
        const uint32_t bstep_ = (uint32_t)(ca_) * 2048;                      \
        ldsm4(ah[sl], aBase + (((c0h_ + aSel) ^ swk) << 4));                 \
        ldsm4(al[sl], aBase + (((c0l_ + aSel) ^ swk) << 4));                 \
        _Pragma("unroll")                                                    \
        for (int q = 0; q < 2; q++) {                                        \
            ldsm4t(bh[sl][q], bOffW[q] + bstep_);                            \
            ldsm4t(bl[sl][q], bOffW[q] + bstep_ + 32768);                    \
        }                                                                    \
    } while (0)

#define RUN_MMA(acc) do {                                                    \
        uint32_t ah[2][4], al[2][4], bh[2][2][4], bl[2][2][4];               \
        LOADCHUNK(0, 0);                                                     \
        _Pragma("unroll 2")                                                  \
        for (int ca = 0; ca < 16; ca++) {                                    \
            const int cur = ca & 1, nxt = cur ^ 1;                           \
            if (ca < 15) LOADCHUNK(nxt, ca + 1);                             \
            _Pragma("unroll")                                                \
            for (int nf = 0; nf < 4; nf++) {                                 \
                const uint32_t* bhf = &bh[cur][nf >> 1][(nf & 1) * 2];       \
                const uint32_t* blf = &bl[cur][nf >> 1][(nf & 1) * 2];       \
                mma16816(acc[nf], ah[cur], bhf);                             \
                mma16816(acc[nf], ah[cur], blf);                             \
                mma16816(acc[nf], al[cur], bhf);                             \
            }                                                                \
        }                                                                    \
    } while (0)

    for (int tick = 1; tick <= NTICK; tick++) {
        const bool active = (role == 0) ? (tick <= NT)
                          : (role == 1) ? (tick >= 2 && tick <= NT + 1)
                                        : (tick >= 3 && tick <= NT + 2);
        // role1 computes y(h1(tick-3)) for ticks where tick-3 in [1, NT]
        const bool yact = (role == 1) && (tick >= 4 && tick <= NT + 3);

        // role1: prefetch h1(tick-3) row for the y-reduction (stable buffer)
        uint2 yh2 = make_uint2(0, 0), yl2 = make_uint2(0, 0);
        if (yact) {
            const uint8_t* H1s = g_H1[(tick - 1) & 1][nu];
            yh2 = __ldcg((const uint2*)(H1s + j * 128 + cg4 * 8));
            yl2 = __ldcg((const uint2*)(H1s + 32768 + j * 128 + cg4 * 8));
        }

        if (active) {
            STAGE_B((role == 2) ? g_H1[(tick - 1) & 1][nu] : g_H0[(tick - 1) & 1][nu]);

            // role2: prefetch this tick's P partials while B lands
            float2 pv0[4], pv1[4];
            if (role == 2) {
                const float* Ps = g_P[tick & 1][pid];
#pragma unroll
                for (int nf = 0; nf < 4; nf++) {
                    int c = cbase + 8 * nf;
                    pv0[nf] = __ldcg((const float2*)(Ps + rowA * 64 + c));
                    pv1[nf] = __ldcg((const float2*)(Ps + (rowA + 8) * 64 + c));
                }
            }

            asm volatile("cp.async.wait_group 0;" ::: "memory");
            __syncthreads();

            float acc[4][4];
#pragma unroll
            for (int nf = 0; nf < 4; nf++)
#pragma unroll
                for (int qq = 0; qq < 4; qq++) acc[nf][qq] = 0.f;
            RUN_MMA(acc);

            if (role == 1) {
                float* Pd = g_P[(tick - 1) & 1][pid];
#pragma unroll
                for (int nf = 0; nf < 4; nf++) {
                    int c = cbase + 8 * nf;
                    __stcg((float2*)(Pd + rowA * 64 + c),
                           make_float2(acc[nf][0], acc[nf][1]));
                    __stcg((float2*)(Pd + (rowA + 8) * 64 + c),
                           make_float2(acc[nf][2], acc[nf][3]));
                }
            } else {
                if (role == 2) {
#pragma unroll
                    for (int nf = 0; nf < 4; nf++) {
                        acc[nf][0] += pv0[nf].x;
                        acc[nf][1] += pv0[nf].y;
                        acc[nf][2] += pv1[nf].x;
                        acc[nf][3] += pv1[nf].y;
                    }
                }
                __syncthreads();   // B reads done before zs overlays B
#pragma unroll
                for (int nf = 0; nf < 4; nf++) {
                    int c = cbase + 8 * nf;
                    *(float2*)(zs + rowA * ZS_STRIDE + c) =
                        make_float2(acc[nf][0], acc[nf][1]);
                    *(float2*)(zs + (rowA + 8) * ZS_STRIDE + c) =
                        make_float2(acc[nf][2], acc[nf][3]);
                }
                __syncthreads();

                // ---- gate nonlinearity + state update (512 thr, 4 cols) ----
                uint8_t* Hb = (role == 0) ? g_H0[tick & 1][nu] : g_H1[tick & 1][nu];
                const int rb = jl * 4;
                float4 zi4 = *(const float4*)(zs + (rb + 0) * ZS_STRIDE + cg4 * 4);
                float4 zf4 = *(const float4*)(zs + (rb + 1) * ZS_STRIDE + cg4 * 4);
                float4 zg4 = *(const float4*)(zs + (rb + 2) * ZS_STRIDE + cg4 * 4);
                float4 zo4 = *(const float4*)(zs + (rb + 3) * ZS_STRIDE + cg4 * 4);
                float ziv[4] = {zi4.x, zi4.y, zi4.z, zi4.w};
                float zfv[4] = {zf4.x, zf4.y, zf4.z, zf4.w};
                float zgv[4] = {zg4.x, zg4.y, zg4.z, zg4.w};
                float zov[4] = {zo4.x, zo4.y, zo4.z, zo4.w};
                float hv[4];
#pragma unroll
                for (int c = 0; c < 4; c++) {
                    float zi = ziv[c] + bias[0];
                    float zf = zfv[c] + bias[1];
                    float zg = zgv[c] + bias[2];
                    float zo = zov[c] + bias[3];
                    cst[c] = sigm(zf) * cst[c] + sigm(zi) * tanh_f(zg);
                    hv[c] = sigm(zo) * tanh_f(cst[c]);
                }
                uint32_t hiu[2], lou[2];
                split2(hv[0], hv[1], hiu[0], lou[0]);
                split2(hv[2], hv[3], hiu[1], lou[1]);
                __stcg((uint2*)(Hb + j * 128 + cg4 * 8),
                       make_uint2(hiu[0], hiu[1]));
                __stcg((uint2*)(Hb + 32768 + j * 128 + cg4 * 8),
                       make_uint2(lou[0], lou[1]));
            }
        }

        // ---- role1: y reduction for h1(tick-3) (all 512 threads) ----
        if (yact) {
            __syncthreads();   // B LDSM reads done before ys overlays B region
            float yv[4];
            yv[0] = (bf_lo(yh2.x) + bf_lo(yl2.x)) * who;
            yv[1] = (bf_hi(yh2.x) + bf_hi(yl2.x)) * who;
            yv[2] = (bf_lo(yh2.y) + bf_lo(yl2.y)) * who;
            yv[3] = (bf_hi(yh2.y) + bf_hi(yl2.y)) * who;
#pragma unroll
            for (int c = 0; c < 4; c++)
                ys[(cg4 * 4 + c) * 33 + jl] = yv[c];
            __syncthreads();
            if (tid < 64) {
                float s = 0.f;
#pragma unroll
                for (int k = 0; k < 32; k++) s += ys[tid * 33 + k];
                __stcg(&g_Y[tick & 1][mu][nbase + tid], s);
            }
        }

        // ---- per-nu barrier: arrive (release), out-summer in shadow, wait ----
        // Y[(tick-1)&1] holds y(h1(tick-4)) -> output column tick-5.
        __syncthreads();
        if (tid == 0) red_release(mybar);

        if (role == 1 && mu == 0 && tick >= 5 && tid >= 64 && tid < 128) {
            int b = tid - 64;
            float s = bho;
#pragma unroll
            for (int m = 0; m < 8; m++)
                s += __ldcg(&g_Y[(tick - 1) & 1][m][nbase + b]);
            out[(nbase + b) * NT + (tick - 5)] = s;
        }

        bar += GRP;
        if (tid == 0) {
            while (ld_acq(mybar) < bar) { }
        }
        __syncthreads();
    }
}

extern "C" void kernel_launch(void* const* d_in, const int* in_sizes, int n_in,
                              void* d_out, int out_size)
{
    (void)in_sizes; (void)n_in; (void)out_size;
    cudaFuncSetAttribute(lstm_mma_kernel,
                         cudaFuncAttributeMaxDynamicSharedMemorySize, SMEM_BYTES);
    void* syncp = nullptr;
    cudaGetSymbolAddress(&syncp, g_sync);
    cudaMemsetAsync(syncp, 0, 5 * 32 * sizeof(unsigned));

    lstm_mma_kernel<<<NCTA, NTHR, SMEM_BYTES>>>(
        (const float*)d_in[0],   // latent
        (const float*)d_in[1],   // W_lh
        (const float*)d_in[2],   // b_lh
        // d_in[3] = W_ih0 unused (layer-0 input is all-zero)
        (const float*)d_in[4],   // W_hh0
        (const float*)d_in[5],   // b_ih0
        (const float*)d_in[6],   // b_hh0
        (const float*)d_in[7],   // W_ih1
        (const float*)d_in[8],   // W_hh1
        (const float*)d_in[9],   // b_ih1
        (const float*)d_in[10],  // b_hh1
        (const float*)d_in[11],  // W_ho
        (const float*)d_in[12],  // b_ho
        (float*)d_out);
}